// round 8
// baseline (speedup 1.0000x reference)
#include <cuda_runtime.h>
#include <cuda_fp16.h>
#include <cstdint>

// Problem constants
#define BB 8192
#define NN 128
#define HH 1024
#define OO 64      // 2*A
#define AA 32
#define TT 8

#define BH ((size_t)BB * HH)
#define BO ((size_t)BB * OO)

// ---------------------------------------------------------------------------
// Scratch (device globals — allocation-free per harness rules)
// ---------------------------------------------------------------------------
__device__ unsigned short g_s1all[TT * BH];      // s1 spikes, row m = b*8 + t, fp16 bits
__device__ unsigned short g_sacc [BH];           // sum_t 2^(t-8) s2(t), fp16 (exact)
__device__ float          g_v3   [BO];
__device__ unsigned short g_w2h[1024 * 2048];    // [N=1024][K=2048] fp16 hi|lo
__device__ unsigned short g_w3h[64 * 2048];      // [N=64]  [K=2048] fp16 hi|lo
__device__ float          g_b3s[OO];             // b3 * 255/256

// ---------------------------------------------------------------------------
// PTX helpers (baseline sm_103 ISA: cp.async, ldmatrix, mma.sync fp16)
// ---------------------------------------------------------------------------
__device__ __forceinline__ uint32_t smem_u32(const void* p) {
    uint32_t a;
    asm("{ .reg .u64 t; cvta.to.shared.u64 t, %1; cvt.u32.u64 %0, t; }" : "=r"(a) : "l"(p));
    return a;
}
__device__ __forceinline__ void cp16(uint32_t dst, const void* src) {
    asm volatile("cp.async.cg.shared.global [%0], [%1], 16;" :: "r"(dst), "l"(src));
}
#define CP_COMMIT() asm volatile("cp.async.commit_group;" ::: "memory")
#define CP_WAIT(n)  asm volatile("cp.async.wait_group %0;" :: "n"(n) : "memory")

__device__ __forceinline__ void ldsm4(uint32_t* r, uint32_t a) {
    asm volatile("ldmatrix.sync.aligned.m8n8.x4.shared.b16 {%0,%1,%2,%3}, [%4];"
                 : "=r"(r[0]), "=r"(r[1]), "=r"(r[2]), "=r"(r[3]) : "r"(a));
}
// fp16 HMMA with fp32 accumulation
__device__ __forceinline__ void mma16816(float* c, const uint32_t* a, const uint32_t* b) {
    asm volatile("mma.sync.aligned.m16n8k16.row.col.f32.f16.f16.f32 "
                 "{%0,%1,%2,%3}, {%4,%5,%6,%7}, {%8,%9}, {%0,%1,%2,%3};"
                 : "+f"(c[0]), "+f"(c[1]), "+f"(c[2]), "+f"(c[3])
                 : "r"(a[0]), "r"(a[1]), "r"(a[2]), "r"(a[3]), "r"(b[0]), "r"(b[1]));
}

// ---------------------------------------------------------------------------
// Weight prep: [N][2048] fp16 K-major; 2-term split w = hi + lo
// ---------------------------------------------------------------------------
__global__ void prep_w2h(const float* __restrict__ w2) {
    int t = blockIdx.x * blockDim.x + threadIdx.x;            // 1M threads
    if (t >= 1024 * 1024) return;
    int n = t & 1023, k = t >> 10;
    float w = w2[(size_t)k * 1024 + n];
    __half hi = __float2half_rn(w);
    __half lo = __float2half_rn(w - __half2float(hi));
    size_t base = (size_t)n * 2048;
    g_w2h[base + k]        = __half_as_ushort(hi);
    g_w2h[base + 1024 + k] = __half_as_ushort(lo);
}
__global__ void prep_w3h(const float* __restrict__ w3, const float* __restrict__ b3) {
    int t = blockIdx.x * blockDim.x + threadIdx.x;            // 64K threads
    if (t >= 64 * 1024) return;
    int n = t & 63, k = t >> 6;
    float w = w3[(size_t)k * 64 + n];
    __half hi = __float2half_rn(w);
    __half lo = __float2half_rn(w - __half2float(hi));
    size_t base = (size_t)n * 2048;
    g_w3h[base + k]        = __half_as_ushort(hi);
    g_w3h[base + 1024 + k] = __half_as_ushort(lo);
    if (t < OO) g_b3s[t] = b3[t] * (255.0f / 256.0f);
}

// ---------------------------------------------------------------------------
// g1 + fire1 fused: u = state@w1 + b1 (fp32 SIMT, k-ascending — bit-identical),
// then all 8 IF-node-1 steps in the epilogue; s1 rows stored as m = b*8 + t.
// ---------------------------------------------------------------------------
__global__ __launch_bounds__(256)
void g1_fire1(const float* __restrict__ A, const float* __restrict__ Bm,
              const float* __restrict__ bias)
{
    constexpr int BM = 128, BN = 64, BK = 32, TM = 8, TN = 4;
    __shared__ float As[BM][BK + 1];
    __shared__ float Bs[BK][BN + 4];
    const int tid = threadIdx.x;
    const int tx = tid % (BN / TN);
    const int ty = tid / (BN / TN);
    const int rowBase = blockIdx.y * BM;
    const int colBase = blockIdx.x * BN;

    float acc[TM][TN];
#pragma unroll
    for (int i = 0; i < TM; i++)
#pragma unroll
        for (int j = 0; j < TN; j++) acc[i][j] = 0.0f;

    for (int k0 = 0; k0 < NN; k0 += BK) {
#pragma unroll
        for (int t = tid; t < BM * BK; t += 256) {
            int r = t >> 5, c = t & 31;
            As[r][c] = A[(size_t)(rowBase + r) * NN + (k0 + c)];
        }
#pragma unroll
        for (int t = tid; t < BK * BN; t += 256) {
            int r = t >> 6, c = t & 63;
            Bs[r][c] = Bm[(size_t)(k0 + r) * HH + (colBase + c)];
        }
        __syncthreads();
#pragma unroll
        for (int kk = 0; kk < BK; kk++) {
            float ra[TM], rb[TN];
#pragma unroll
            for (int i = 0; i < TM; i++) ra[i] = As[ty * TM + i][kk];
#pragma unroll
            for (int j = 0; j < TN; j++) rb[j] = Bs[kk][tx * TN + j];
#pragma unroll
            for (int i = 0; i < TM; i++)
#pragma unroll
                for (int j = 0; j < TN; j++)
                    acc[i][j] += ra[i] * rb[j];
        }
        __syncthreads();
    }

#pragma unroll
    for (int i = 0; i < TM; i++) {
        int r = rowBase + ty * TM + i;
#pragma unroll
        for (int j = 0; j < TN; j++) {
            int c = colBase + tx * TN + j;
            float u = acc[i][j] + bias[c];
            float v1 = 0.0f;
#pragma unroll
            for (int t = 0; t < TT; ++t) {
                float h = v1 + u;
                bool s = (h >= 1.0f);
                v1 = s ? 0.0f : h;
                // row m = r*8 + t  (batch-major, timestep interleaved)
                g_s1all[((size_t)r * TT + t) * HH + c] = s ? 0x3C00 : 0;
            }
        }
    }
}

// ---------------------------------------------------------------------------
// Big fp16 HMMA GEMM with FUSED fire2 scan:
//   X2[m=b*8+t][n] = s1all @ w2h^T (K=2048, A wraps mod 1024)
//   epilogue: per (b, n), scan t=0..7 of the fragment via warp shuffles:
//     h = (v2 + x) + b2[n]; s = h>=1; v2 = s?0:h; sacc += s * 2^(t-8)
//   writes only sacc (fp16-exact). x2 never touches GMEM.
// BM=128, BN=128, BK=64, 256 threads (8 warps 4x2), 3-stage cp.async.
// ---------------------------------------------------------------------------
__global__ __launch_bounds__(256)
void gemm_big(const unsigned short* __restrict__ A,
              const unsigned short* __restrict__ Bt,
              const float* __restrict__ b2,
              unsigned short* __restrict__ saccp)
{
    constexpr int BM = 128, BN = 128, BK = 64;
    constexpr int KTOT = 2048, AK = 1024;
    constexpr int NIT = KTOT / BK;        // 32
    constexpr int STAGES = 3;
    constexpr int ATB = BM * 128;         // 16384
    constexpr int BTB = BN * 128;         // 16384
    constexpr int STAGE = ATB + BTB;      // 32768

    extern __shared__ char dsm[];
    const uint32_t sbase = smem_u32(dsm);

    const int tid = threadIdx.x;
    const int wid = tid >> 5;
    const int lane = tid & 31;
    const int wm = wid & 3;               // M: wm*32
    const int wn = wid >> 2;              // N: wn*64
    const int rowBase = blockIdx.y * BM;
    const int colBase = blockIdx.x * BN;

    auto load_tile = [&](int buf, int it) {
        const uint32_t sA = sbase + buf * STAGE;
        const uint32_t sB = sA + ATB;
        const int kb = it * BK;
        const int kA = kb & (AK - 1);
#pragma unroll
        for (int i = 0; i < (BM * 8) / 256; ++i) {     // 4
            int idx = i * 256 + tid;
            int r = idx >> 3, q = idx & 7;
            const void* src = A + (size_t)(rowBase + r) * AK + kA + q * 8;
            cp16(sA + r * 128 + ((q ^ (r & 7)) << 4), src);
        }
#pragma unroll
        for (int i = 0; i < (BN * 8) / 256; ++i) {     // 4
            int idx = i * 256 + tid;
            int r = idx >> 3, q = idx & 7;
            const void* src = Bt + (size_t)(colBase + r) * KTOT + kb + q * 8;
            cp16(sB + r * 128 + ((q ^ (r & 7)) << 4), src);
        }
    };

    float acc[2][8][4];
#pragma unroll
    for (int mt = 0; mt < 2; ++mt)
#pragma unroll
        for (int nt = 0; nt < 8; ++nt)
#pragma unroll
            for (int x = 0; x < 4; ++x) acc[mt][nt][x] = 0.0f;

#pragma unroll
    for (int p = 0; p < STAGES - 1; ++p) { load_tile(p, p); CP_COMMIT(); }

    const int rA0 = wm * 32 + (lane & 15);
    const int qAsel = lane >> 4;
    const int nB0 = wn * 64 + ((lane >> 4) << 3) + (lane & 7);
    const int qBsel = (lane >> 3) & 1;

    for (int it = 0; it < NIT; ++it) {
        CP_WAIT(1);
        __syncthreads();
        if (it + STAGES - 1 < NIT) load_tile((it + STAGES - 1) % STAGES, it + STAGES - 1);
        CP_COMMIT();

        const uint32_t sA = sbase + (it % STAGES) * STAGE;
        const uint32_t sB = sA + ATB;

#pragma unroll
        for (int s = 0; s < 4; ++s) {
            uint32_t a[2][4];
#pragma unroll
            for (int mt = 0; mt < 2; ++mt) {
                int r = rA0 + mt * 16;
                int q = 2 * s + qAsel;
                ldsm4(a[mt], sA + r * 128 + ((q ^ (r & 7)) << 4));
            }
            uint32_t b[8][2];
#pragma unroll
            for (int j = 0; j < 8; j += 2) {
                int n = nB0 + j * 8;
                int q = 2 * s + qBsel;
                uint32_t t4[4];
                ldsm4(t4, sB + n * 128 + ((q ^ (n & 7)) << 4));
                b[j][0] = t4[0]; b[j][1] = t4[1];
                b[j + 1][0] = t4[2]; b[j + 1][1] = t4[3];
            }
#pragma unroll
            for (int mt = 0; mt < 2; ++mt)
#pragma unroll
                for (int nt = 0; nt < 8; ++nt)
                    mma16816(acc[mt][nt], a[mt], b[nt]);
        }
    }

    // ---- fused fire2 epilogue ----
    // fragment row m = wm*32 + mt*16 + (lane>>2) + 8*(j>>1)
    //   => t = lane>>2, b_local = wm*4 + mt*2 + (j>>1)
    // fragment col = colBase + wn*64 + nt*8 + (lane&3)*2 + (j&1)
    const int bBase = rowBase >> 3;          // 16 batch rows per CTA
    const uint32_t fullm = 0xffffffffu;
#pragma unroll
    for (int mt = 0; mt < 2; ++mt) {
#pragma unroll
        for (int nt = 0; nt < 8; ++nt) {
            int c0 = colBase + wn * 64 + nt * 8 + (lane & 3) * 2;
            float bi0 = b2[c0], bi1 = b2[c0 + 1];
#pragma unroll
            for (int j = 0; j < 4; ++j) {
                float bi = (j & 1) ? bi1 : bi0;
                float v2 = 0.0f, sc = 0.0f;
#pragma unroll
                for (int t = 0; t < TT; ++t) {
                    float xt = __shfl_sync(fullm, acc[mt][nt][j], (t << 2) | (lane & 3));
                    float h = v2 + xt;       // (v2 + M)
                    h = h + bi;              // ... + b2   (matches reference order)
                    bool s = (h >= 1.0f);
                    v2 = s ? 0.0f : h;
                    if (s) sc += (float)(1 << t) * (1.0f / 256.0f);
                }
                if ((lane >> 2) == 0) {
                    int b = bBase + wm * 4 + mt * 2 + (j >> 1);
                    int c = c0 + (j & 1);
                    saccp[(size_t)b * HH + c] = __half_as_ushort(__float2half_rn(sc));
                }
            }
        }
    }
}

// ---------------------------------------------------------------------------
// Small fp16 GEMM for g3: v3 = sacc @ w3h^T + b3s.  K=2048 (hi|lo).
// ---------------------------------------------------------------------------
__global__ __launch_bounds__(256)
void gemm_g3(const unsigned short* __restrict__ A,
             const unsigned short* __restrict__ Bt,
             const float* __restrict__ bias,
             float* __restrict__ outp)
{
    constexpr int BM = 128, BN = 64, BK = 64;
    constexpr int KTOT = 2048, AK = 1024;
    constexpr int NIT = KTOT / BK;        // 32
    constexpr int STAGES = 3;
    constexpr int ATB = BM * 128;
    constexpr int BTB = BN * 128;
    constexpr int STAGE = ATB + BTB;
    constexpr int WTM = 16;

    extern __shared__ char dsm[];
    const uint32_t sbase = smem_u32(dsm);

    const int tid = threadIdx.x;
    const int wid = tid >> 5;
    const int lane = tid & 31;
    const int wm = wid;
    const int rowBase = blockIdx.y * BM;

    auto load_tile = [&](int buf, int it) {
        const uint32_t sA = sbase + buf * STAGE;
        const uint32_t sB = sA + ATB;
        const int kb = it * BK;
        const int kA = kb & (AK - 1);
#pragma unroll
        for (int i = 0; i < (BM * 8) / 256; ++i) {
            int idx = i * 256 + tid;
            int r = idx >> 3, q = idx & 7;
            const void* src = A + (size_t)(rowBase + r) * AK + kA + q * 8;
            cp16(sA + r * 128 + ((q ^ (r & 7)) << 4), src);
        }
#pragma unroll
        for (int i = 0; i < (BN * 8) / 256; ++i) {
            int idx = i * 256 + tid;
            int r = idx >> 3, q = idx & 7;
            const void* src = Bt + (size_t)r * KTOT + kb + q * 8;
            cp16(sB + r * 128 + ((q ^ (r & 7)) << 4), src);
        }
    };

    float acc[8][4];
#pragma unroll
    for (int nt = 0; nt < 8; ++nt)
#pragma unroll
        for (int x = 0; x < 4; ++x) acc[nt][x] = 0.0f;

#pragma unroll
    for (int p = 0; p < STAGES - 1; ++p) { load_tile(p, p); CP_COMMIT(); }

    const int rA0 = wm * WTM + (lane & 15);
    const int qAsel = lane >> 4;
    const int nB0 = (lane >> 4) * 8 + (lane & 7);
    const int qBsel = (lane >> 3) & 1;

    for (int it = 0; it < NIT; ++it) {
        CP_WAIT(1);
        __syncthreads();
        if (it + STAGES - 1 < NIT) load_tile((it + STAGES - 1) % STAGES, it + STAGES - 1);
        CP_COMMIT();

        const uint32_t sA = sbase + (it % STAGES) * STAGE;
        const uint32_t sB = sA + ATB;

#pragma unroll
        for (int s = 0; s < 4; ++s) {
            uint32_t a[4];
            {
                int r = rA0;
                int q = 2 * s + qAsel;
                ldsm4(a, sA + r * 128 + ((q ^ (r & 7)) << 4));
            }
            uint32_t b[8][2];
#pragma unroll
            for (int j = 0; j < 8; j += 2) {
                int n = nB0 + j * 8;
                int q = 2 * s + qBsel;
                uint32_t t4[4];
                ldsm4(t4, sB + n * 128 + ((q ^ (n & 7)) << 4));
                b[j][0] = t4[0]; b[j][1] = t4[1];
                b[j + 1][0] = t4[2]; b[j + 1][1] = t4[3];
            }
#pragma unroll
            for (int nt = 0; nt < 8; ++nt)
                mma16816(acc[nt], a, b[nt]);
        }
    }

    int r0 = rowBase + wm * WTM + (lane >> 2);
#pragma unroll
    for (int nt = 0; nt < 8; ++nt) {
        int c = nt * 8 + (lane & 3) * 2;
        float bi0 = bias[c], bi1 = bias[c + 1];
#pragma unroll
        for (int hrow = 0; hrow < 2; ++hrow) {
            int r = r0 + hrow * 8;
            size_t idx = (size_t)r * OO + c;
            float2 o;
            o.x = acc[nt][hrow * 2 + 0] + bi0;
            o.y = acc[nt][hrow * 2 + 1] + bi1;
            *reinterpret_cast<float2*>(outp + idx) = o;
        }
    }
}

// ---------------------------------------------------------------------------
// Final tanh-Gaussian epilogue. One warp per batch row.
// ---------------------------------------------------------------------------
__global__ void finalize_kernel(const float* __restrict__ eps, float* __restrict__ out) {
    int warp = (blockIdx.x * blockDim.x + threadIdx.x) >> 5;
    int lane = threadIdx.x & 31;
    if (warp >= BB) return;
    const float* v3r = g_v3 + (size_t)warp * OO;
    float mu = v3r[lane];
    float ls = v3r[AA + lane];
    ls = fminf(fmaxf(ls, -20.0f), 2.0f);
    float sd = expf(ls);
    float e  = eps[(size_t)warp * AA + lane];
    float z  = mu + sd * e;
    float a  = tanhf(z);
    out[(size_t)warp * AA + lane] = a;
    float lp = -0.5f * e * e - ls - 0.91893853320467274f
               - logf(1.0f - a * a + 1e-7f);
#pragma unroll
    for (int o = 16; o > 0; o >>= 1) lp += __shfl_down_sync(0xffffffffu, lp, o);
    if (lane == 0) out[(size_t)BB * AA + warp] = lp;
}

// ---------------------------------------------------------------------------
extern "C" void kernel_launch(void* const* d_in, const int* in_sizes, int n_in,
                              void* d_out, int out_size)
{
    const float* state = (const float*)d_in[0];
    const float* w1    = (const float*)d_in[1];
    const float* b1    = (const float*)d_in[2];
    const float* w2    = (const float*)d_in[3];
    const float* b2    = (const float*)d_in[4];
    const float* w3    = (const float*)d_in[5];
    const float* b3    = (const float*)d_in[6];
    const float* eps   = (const float*)d_in[7];
    float* out = (float*)d_out;

    float* v3 = nullptr;
    unsigned short* s1all = nullptr; unsigned short* sacc = nullptr;
    unsigned short* w2h = nullptr; unsigned short* w3h = nullptr;
    float* b3s = nullptr;
    cudaGetSymbolAddress((void**)&v3,    g_v3);
    cudaGetSymbolAddress((void**)&s1all, g_s1all);
    cudaGetSymbolAddress((void**)&sacc,  g_sacc);
    cudaGetSymbolAddress((void**)&w2h,   g_w2h);
    cudaGetSymbolAddress((void**)&w3h,   g_w3h);
    cudaGetSymbolAddress((void**)&b3s,   g_b3s);

    const int SMBIG = 3 * (128 * 128 + 128 * 128); // 98304
    const int SMG3  = 3 * (128 * 128 + 64 * 128);  // 73728
    cudaFuncSetAttribute(gemm_big, cudaFuncAttributeMaxDynamicSharedMemorySize, SMBIG);
    cudaFuncSetAttribute(gemm_g3,  cudaFuncAttributeMaxDynamicSharedMemorySize, SMG3);

    // 1) weight prep (2-term fp16 split, K-major transpose)
    prep_w2h<<<(1024 * 1024) / 256, 256>>>(w2);
    prep_w3h<<<(64 * 1024) / 256, 256>>>(w3, b3);

    // 2) g1 + all 8 fire1 steps fused (u never hits GMEM; (b,t)-interleaved s1)
    {
        dim3 grid(HH / 64, BB / 128);
        g1_fire1<<<grid, 256>>>(state, w1, b1);
    }

    // 3) ONE big fp16 GEMM with fused fire2 scan -> writes sacc directly
    {
        dim3 grid(HH / 128, (TT * BB) / 128);
        gemm_big<<<grid, 256, SMBIG>>>(s1all, w2h, b2, sacc);
    }

    // 4) ONE small GEMM: v3 = sacc @ w3 + (255/256) b3
    {
        dim3 grid(1, BB / 128);
        gemm_g3<<<grid, 256, SMG3>>>(sacc, w3h, b3s, v3);
    }

    // 5) tanh-Gaussian head
    finalize_kernel<<<BB / 8, 256>>>(eps, out);
}

// round 9
// speedup vs baseline: 1.3289x; 1.3289x over previous
#include <cuda_runtime.h>
#include <cuda_fp16.h>
#include <cstdint>

// Problem constants
#define BB 8192
#define NN 128
#define HH 1024
#define OO 64      // 2*A
#define AA 32
#define TT 8

#define BH ((size_t)BB * HH)
#define BO ((size_t)BB * OO)

// ---------------------------------------------------------------------------
// Scratch (device globals — allocation-free per harness rules)
// ---------------------------------------------------------------------------
__device__ unsigned short g_s1all[TT * BH];      // s1 spikes, row m = b*8 + t, fp16 bits
__device__ unsigned short g_sacc [BH];           // sum_t 2^(t-8) s2(t), fp16 (exact)
__device__ float          g_v3   [BO];
__device__ unsigned short g_w2h[1024 * 2048];    // [N=1024][K=2048] fp16 hi|lo
__device__ unsigned short g_w3h[64 * 2048];      // [N=64]  [K=2048] fp16 hi|lo
__device__ float          g_b3s[OO];             // b3 * 255/256

// ---------------------------------------------------------------------------
// PTX helpers (baseline sm_103 ISA: cp.async, ldmatrix, mma.sync fp16)
// ---------------------------------------------------------------------------
__device__ __forceinline__ uint32_t smem_u32(const void* p) {
    uint32_t a;
    asm("{ .reg .u64 t; cvta.to.shared.u64 t, %1; cvt.u32.u64 %0, t; }" : "=r"(a) : "l"(p));
    return a;
}
__device__ __forceinline__ void cp16(uint32_t dst, const void* src) {
    asm volatile("cp.async.cg.shared.global [%0], [%1], 16;" :: "r"(dst), "l"(src));
}
#define CP_COMMIT() asm volatile("cp.async.commit_group;" ::: "memory")
#define CP_WAIT(n)  asm volatile("cp.async.wait_group %0;" :: "n"(n) : "memory")

__device__ __forceinline__ void ldsm4(uint32_t* r, uint32_t a) {
    asm volatile("ldmatrix.sync.aligned.m8n8.x4.shared.b16 {%0,%1,%2,%3}, [%4];"
                 : "=r"(r[0]), "=r"(r[1]), "=r"(r[2]), "=r"(r[3]) : "r"(a));
}
// fp16 HMMA with fp32 accumulation
__device__ __forceinline__ void mma16816(float* c, const uint32_t* a, const uint32_t* b) {
    asm volatile("mma.sync.aligned.m16n8k16.row.col.f32.f16.f16.f32 "
                 "{%0,%1,%2,%3}, {%4,%5,%6,%7}, {%8,%9}, {%0,%1,%2,%3};"
                 : "+f"(c[0]), "+f"(c[1]), "+f"(c[2]), "+f"(c[3])
                 : "r"(a[0]), "r"(a[1]), "r"(a[2]), "r"(a[3]), "r"(b[0]), "r"(b[1]));
}

// ---------------------------------------------------------------------------
// Weight prep: [N][2048] fp16 K-major; 2-term split w = hi + lo
// ---------------------------------------------------------------------------
__global__ void prep_w2h(const float* __restrict__ w2) {
    int t = blockIdx.x * blockDim.x + threadIdx.x;            // 1M threads
    if (t >= 1024 * 1024) return;
    int n = t & 1023, k = t >> 10;
    float w = w2[(size_t)k * 1024 + n];
    __half hi = __float2half_rn(w);
    __half lo = __float2half_rn(w - __half2float(hi));
    size_t base = (size_t)n * 2048;
    g_w2h[base + k]        = __half_as_ushort(hi);
    g_w2h[base + 1024 + k] = __half_as_ushort(lo);
}
__global__ void prep_w3h(const float* __restrict__ w3, const float* __restrict__ b3) {
    int t = blockIdx.x * blockDim.x + threadIdx.x;            // 64K threads
    if (t >= 64 * 1024) return;
    int n = t & 63, k = t >> 6;
    float w = w3[(size_t)k * 64 + n];
    __half hi = __float2half_rn(w);
    __half lo = __float2half_rn(w - __half2float(hi));
    size_t base = (size_t)n * 2048;
    g_w3h[base + k]        = __half_as_ushort(hi);
    g_w3h[base + 1024 + k] = __half_as_ushort(lo);
    if (t < OO) g_b3s[t] = b3[t] * (255.0f / 256.0f);
}

// ---------------------------------------------------------------------------
// g1 + fire1 fused: u = state@w1 + b1 (fp32 SIMT, k-ascending — bit-identical),
// then all 8 IF-node-1 steps in the epilogue; s1 rows stored as m = b*8 + t.
// ---------------------------------------------------------------------------
__global__ __launch_bounds__(256)
void g1_fire1(const float* __restrict__ A, const float* __restrict__ Bm,
              const float* __restrict__ bias)
{
    constexpr int BM = 128, BN = 64, BK = 32, TM = 8, TN = 4;
    __shared__ float As[BM][BK + 1];
    __shared__ float Bs[BK][BN + 4];
    const int tid = threadIdx.x;
    const int tx = tid % (BN / TN);
    const int ty = tid / (BN / TN);
    const int rowBase = blockIdx.y * BM;
    const int colBase = blockIdx.x * BN;

    float acc[TM][TN];
#pragma unroll
    for (int i = 0; i < TM; i++)
#pragma unroll
        for (int j = 0; j < TN; j++) acc[i][j] = 0.0f;

    for (int k0 = 0; k0 < NN; k0 += BK) {
#pragma unroll
        for (int t = tid; t < BM * BK; t += 256) {
            int r = t >> 5, c = t & 31;
            As[r][c] = A[(size_t)(rowBase + r) * NN + (k0 + c)];
        }
#pragma unroll
        for (int t = tid; t < BK * BN; t += 256) {
            int r = t >> 6, c = t & 63;
            Bs[r][c] = Bm[(size_t)(k0 + r) * HH + (colBase + c)];
        }
        __syncthreads();
#pragma unroll
        for (int kk = 0; kk < BK; kk++) {
            float ra[TM], rb[TN];
#pragma unroll
            for (int i = 0; i < TM; i++) ra[i] = As[ty * TM + i][kk];
#pragma unroll
            for (int j = 0; j < TN; j++) rb[j] = Bs[kk][tx * TN + j];
#pragma unroll
            for (int i = 0; i < TM; i++)
#pragma unroll
                for (int j = 0; j < TN; j++)
                    acc[i][j] += ra[i] * rb[j];
        }
        __syncthreads();
    }

#pragma unroll
    for (int i = 0; i < TM; i++) {
        int r = rowBase + ty * TM + i;
#pragma unroll
        for (int j = 0; j < TN; j++) {
            int c = colBase + tx * TN + j;
            float u = acc[i][j] + bias[c];
            float v1 = 0.0f;
#pragma unroll
            for (int t = 0; t < TT; ++t) {
                float h = v1 + u;
                bool s = (h >= 1.0f);
                v1 = s ? 0.0f : h;
                // row m = r*8 + t  (batch-major, timestep interleaved)
                g_s1all[((size_t)r * TT + t) * HH + c] = s ? 0x3C00 : 0;
            }
        }
    }
}

// ---------------------------------------------------------------------------
// Big fp16 HMMA GEMM with FUSED fire2 scan via SMEM round-trip:
//   X2[m=b*8+t][n] = s1all @ w2h^T (K=2048, A wraps mod 1024)
//   epilogue: dump acc tile to smem (pipeline buffers are dead), then each
//   thread scans 8 (b, n) columns over t with the exact fire2 fp32 sequence:
//     h = (v2 + x) + b2[n]; s = h>=1; v2 = s?0:h; sacc += s * 2^(t-8)
//   writes only sacc (fp16-exact m/256 values). x2 never touches GMEM.
// BM=128, BN=128, BK=64, 256 threads (8 warps 4x2), 3-stage cp.async.
// ---------------------------------------------------------------------------
#define EPAD 132   // padded row length (floats) for the epilogue tile

__global__ __launch_bounds__(256, 2)
void gemm_big(const unsigned short* __restrict__ A,
              const unsigned short* __restrict__ Bt,
              const float* __restrict__ b2,
              unsigned short* __restrict__ saccp)
{
    constexpr int BM = 128, BN = 128, BK = 64;
    constexpr int KTOT = 2048, AK = 1024;
    constexpr int NIT = KTOT / BK;        // 32
    constexpr int STAGES = 3;
    constexpr int ATB = BM * 128;         // 16384
    constexpr int BTB = BN * 128;         // 16384
    constexpr int STAGE = ATB + BTB;      // 32768

    extern __shared__ char dsm[];
    const uint32_t sbase = smem_u32(dsm);

    const int tid = threadIdx.x;
    const int wid = tid >> 5;
    const int lane = tid & 31;
    const int wm = wid & 3;               // M: wm*32
    const int wn = wid >> 2;              // N: wn*64
    const int rowBase = blockIdx.y * BM;
    const int colBase = blockIdx.x * BN;

    auto load_tile = [&](int buf, int it) {
        const uint32_t sA = sbase + buf * STAGE;
        const uint32_t sB = sA + ATB;
        const int kb = it * BK;
        const int kA = kb & (AK - 1);
#pragma unroll
        for (int i = 0; i < (BM * 8) / 256; ++i) {     // 4
            int idx = i * 256 + tid;
            int r = idx >> 3, q = idx & 7;
            const void* src = A + (size_t)(rowBase + r) * AK + kA + q * 8;
            cp16(sA + r * 128 + ((q ^ (r & 7)) << 4), src);
        }
#pragma unroll
        for (int i = 0; i < (BN * 8) / 256; ++i) {     // 4
            int idx = i * 256 + tid;
            int r = idx >> 3, q = idx & 7;
            const void* src = Bt + (size_t)(colBase + r) * KTOT + kb + q * 8;
            cp16(sB + r * 128 + ((q ^ (r & 7)) << 4), src);
        }
    };

    float acc[2][8][4];
#pragma unroll
    for (int mt = 0; mt < 2; ++mt)
#pragma unroll
        for (int nt = 0; nt < 8; ++nt)
#pragma unroll
            for (int x = 0; x < 4; ++x) acc[mt][nt][x] = 0.0f;

#pragma unroll
    for (int p = 0; p < STAGES - 1; ++p) { load_tile(p, p); CP_COMMIT(); }

    const int rA0 = wm * 32 + (lane & 15);
    const int qAsel = lane >> 4;
    const int nB0 = wn * 64 + ((lane >> 4) << 3) + (lane & 7);
    const int qBsel = (lane >> 3) & 1;

    for (int it = 0; it < NIT; ++it) {
        CP_WAIT(1);
        __syncthreads();
        if (it + STAGES - 1 < NIT) load_tile((it + STAGES - 1) % STAGES, it + STAGES - 1);
        CP_COMMIT();

        const uint32_t sA = sbase + (it % STAGES) * STAGE;
        const uint32_t sB = sA + ATB;

#pragma unroll
        for (int s = 0; s < 4; ++s) {
            uint32_t a[2][4];
#pragma unroll
            for (int mt = 0; mt < 2; ++mt) {
                int r = rA0 + mt * 16;
                int q = 2 * s + qAsel;
                ldsm4(a[mt], sA + r * 128 + ((q ^ (r & 7)) << 4));
            }
            uint32_t b[8][2];
#pragma unroll
            for (int j = 0; j < 8; j += 2) {
                int n = nB0 + j * 8;
                int q = 2 * s + qBsel;
                uint32_t t4[4];
                ldsm4(t4, sB + n * 128 + ((q ^ (n & 7)) << 4));
                b[j][0] = t4[0]; b[j][1] = t4[1];
                b[j + 1][0] = t4[2]; b[j + 1][1] = t4[3];
            }
#pragma unroll
            for (int mt = 0; mt < 2; ++mt)
#pragma unroll
                for (int nt = 0; nt < 8; ++nt)
                    mma16816(acc[mt][nt], a[mt], b[nt]);
        }
    }

    // ---- fused fire2 epilogue via smem (pipeline buffers are dead) ----
    CP_WAIT(0);
    __syncthreads();
    float* sx = reinterpret_cast<float*>(dsm);   // [128][EPAD] fp32 tile

    // dump acc: fragment row m = wm*32 + mt*16 + (lane>>2) + 8*hrow,
    //           col c = wn*64 + nt*8 + (lane&3)*2
#pragma unroll
    for (int mt = 0; mt < 2; ++mt) {
#pragma unroll
        for (int nt = 0; nt < 8; ++nt) {
            int c = wn * 64 + nt * 8 + (lane & 3) * 2;
#pragma unroll
            for (int hrow = 0; hrow < 2; ++hrow) {
                int m = wm * 32 + mt * 16 + (lane >> 2) + hrow * 8;
                float2 v;
                v.x = acc[mt][nt][hrow * 2 + 0];
                v.y = acc[mt][nt][hrow * 2 + 1];
                *reinterpret_cast<float2*>(&sx[m * EPAD + c]) = v;
            }
        }
    }
    __syncthreads();

    // scan: 16 batch rows x 128 cols = 2048 scans, 8 per thread
    const int bBase = rowBase >> 3;
#pragma unroll
    for (int idx = 0; idx < 8; ++idx) {
        int flat = idx * 256 + tid;
        int bl = flat >> 7;            // 0..15
        int cl = flat & 127;           // 0..127
        float bi = b2[colBase + cl];
        float v2 = 0.0f, sc = 0.0f;
#pragma unroll
        for (int t = 0; t < TT; ++t) {
            float x = sx[(bl * 8 + t) * EPAD + cl];
            float h = v2 + x;          // (v2 + M)
            h = h + bi;                // ... + b2   (matches reference order)
            bool s = (h >= 1.0f);
            v2 = s ? 0.0f : h;
            if (s) sc += (float)(1 << t) * (1.0f / 256.0f);
        }
        saccp[(size_t)(bBase + bl) * HH + colBase + cl] =
            __half_as_ushort(__float2half_rn(sc));   // exact (m/256)
    }
}

// ---------------------------------------------------------------------------
// Small fp16 GEMM for g3: v3 = sacc @ w3h^T + b3s.  K=2048 (hi|lo).
// ---------------------------------------------------------------------------
__global__ __launch_bounds__(256)
void gemm_g3(const unsigned short* __restrict__ A,
             const unsigned short* __restrict__ Bt,
             const float* __restrict__ bias,
             float* __restrict__ outp)
{
    constexpr int BM = 128, BN = 64, BK = 64;
    constexpr int KTOT = 2048, AK = 1024;
    constexpr int NIT = KTOT / BK;        // 32
    constexpr int STAGES = 3;
    constexpr int ATB = BM * 128;
    constexpr int BTB = BN * 128;
    constexpr int STAGE = ATB + BTB;
    constexpr int WTM = 16;

    extern __shared__ char dsm[];
    const uint32_t sbase = smem_u32(dsm);

    const int tid = threadIdx.x;
    const int wid = tid >> 5;
    const int lane = tid & 31;
    const int wm = wid;
    const int rowBase = blockIdx.y * BM;

    auto load_tile = [&](int buf, int it) {
        const uint32_t sA = sbase + buf * STAGE;
        const uint32_t sB = sA + ATB;
        const int kb = it * BK;
        const int kA = kb & (AK - 1);
#pragma unroll
        for (int i = 0; i < (BM * 8) / 256; ++i) {
            int idx = i * 256 + tid;
            int r = idx >> 3, q = idx & 7;
            const void* src = A + (size_t)(rowBase + r) * AK + kA + q * 8;
            cp16(sA + r * 128 + ((q ^ (r & 7)) << 4), src);
        }
#pragma unroll
        for (int i = 0; i < (BN * 8) / 256; ++i) {
            int idx = i * 256 + tid;
            int r = idx >> 3, q = idx & 7;
            const void* src = Bt + (size_t)r * KTOT + kb + q * 8;
            cp16(sB + r * 128 + ((q ^ (r & 7)) << 4), src);
        }
    };

    float acc[8][4];
#pragma unroll
    for (int nt = 0; nt < 8; ++nt)
#pragma unroll
        for (int x = 0; x < 4; ++x) acc[nt][x] = 0.0f;

#pragma unroll
    for (int p = 0; p < STAGES - 1; ++p) { load_tile(p, p); CP_COMMIT(); }

    const int rA0 = wm * WTM + (lane & 15);
    const int qAsel = lane >> 4;
    const int nB0 = (lane >> 4) * 8 + (lane & 7);
    const int qBsel = (lane >> 3) & 1;

    for (int it = 0; it < NIT; ++it) {
        CP_WAIT(1);
        __syncthreads();
        if (it + STAGES - 1 < NIT) load_tile((it + STAGES - 1) % STAGES, it + STAGES - 1);
        CP_COMMIT();

        const uint32_t sA = sbase + (it % STAGES) * STAGE;
        const uint32_t sB = sA + ATB;

#pragma unroll
        for (int s = 0; s < 4; ++s) {
            uint32_t a[4];
            {
                int r = rA0;
                int q = 2 * s + qAsel;
                ldsm4(a, sA + r * 128 + ((q ^ (r & 7)) << 4));
            }
            uint32_t b[8][2];
#pragma unroll
            for (int j = 0; j < 8; j += 2) {
                int n = nB0 + j * 8;
                int q = 2 * s + qBsel;
                uint32_t t4[4];
                ldsm4(t4, sB + n * 128 + ((q ^ (n & 7)) << 4));
                b[j][0] = t4[0]; b[j][1] = t4[1];
                b[j + 1][0] = t4[2]; b[j + 1][1] = t4[3];
            }
#pragma unroll
            for (int nt = 0; nt < 8; ++nt)
                mma16816(acc[nt], a, b[nt]);
        }
    }

    int r0 = rowBase + wm * WTM + (lane >> 2);
#pragma unroll
    for (int nt = 0; nt < 8; ++nt) {
        int c = nt * 8 + (lane & 3) * 2;
        float bi0 = bias[c], bi1 = bias[c + 1];
#pragma unroll
        for (int hrow = 0; hrow < 2; ++hrow) {
            int r = r0 + hrow * 8;
            size_t idx = (size_t)r * OO + c;
            float2 o;
            o.x = acc[nt][hrow * 2 + 0] + bi0;
            o.y = acc[nt][hrow * 2 + 1] + bi1;
            *reinterpret_cast<float2*>(outp + idx) = o;
        }
    }
}

// ---------------------------------------------------------------------------
// Final tanh-Gaussian epilogue. One warp per batch row.
// ---------------------------------------------------------------------------
__global__ void finalize_kernel(const float* __restrict__ eps, float* __restrict__ out) {
    int warp = (blockIdx.x * blockDim.x + threadIdx.x) >> 5;
    int lane = threadIdx.x & 31;
    if (warp >= BB) return;
    const float* v3r = g_v3 + (size_t)warp * OO;
    float mu = v3r[lane];
    float ls = v3r[AA + lane];
    ls = fminf(fmaxf(ls, -20.0f), 2.0f);
    float sd = expf(ls);
    float e  = eps[(size_t)warp * AA + lane];
    float z  = mu + sd * e;
    float a  = tanhf(z);
    out[(size_t)warp * AA + lane] = a;
    float lp = -0.5f * e * e - ls - 0.91893853320467274f
               - logf(1.0f - a * a + 1e-7f);
#pragma unroll
    for (int o = 16; o > 0; o >>= 1) lp += __shfl_down_sync(0xffffffffu, lp, o);
    if (lane == 0) out[(size_t)BB * AA + warp] = lp;
}

// ---------------------------------------------------------------------------
extern "C" void kernel_launch(void* const* d_in, const int* in_sizes, int n_in,
                              void* d_out, int out_size)
{
    const float* state = (const float*)d_in[0];
    const float* w1    = (const float*)d_in[1];
    const float* b1    = (const float*)d_in[2];
    const float* w2    = (const float*)d_in[3];
    const float* b2    = (const float*)d_in[4];
    const float* w3    = (const float*)d_in[5];
    const float* b3    = (const float*)d_in[6];
    const float* eps   = (const float*)d_in[7];
    float* out = (float*)d_out;

    float* v3 = nullptr;
    unsigned short* s1all = nullptr; unsigned short* sacc = nullptr;
    unsigned short* w2h = nullptr; unsigned short* w3h = nullptr;
    float* b3s = nullptr;
    cudaGetSymbolAddress((void**)&v3,    g_v3);
    cudaGetSymbolAddress((void**)&s1all, g_s1all);
    cudaGetSymbolAddress((void**)&sacc,  g_sacc);
    cudaGetSymbolAddress((void**)&w2h,   g_w2h);
    cudaGetSymbolAddress((void**)&w3h,   g_w3h);
    cudaGetSymbolAddress((void**)&b3s,   g_b3s);

    const int SMBIG = 3 * (128 * 128 + 128 * 128); // 98304 (>= 128*EPAD*4 = 67584)
    const int SMG3  = 3 * (128 * 128 + 64 * 128);  // 73728
    cudaFuncSetAttribute(gemm_big, cudaFuncAttributeMaxDynamicSharedMemorySize, SMBIG);
    cudaFuncSetAttribute(gemm_g3,  cudaFuncAttributeMaxDynamicSharedMemorySize, SMG3);

    // 1) weight prep (2-term fp16 split, K-major transpose)
    prep_w2h<<<(1024 * 1024) / 256, 256>>>(w2);
    prep_w3h<<<(64 * 1024) / 256, 256>>>(w3, b3);

    // 2) g1 + all 8 fire1 steps fused (u never hits GMEM; (b,t)-interleaved s1)
    {
        dim3 grid(HH / 64, BB / 128);
        g1_fire1<<<grid, 256>>>(state, w1, b1);
    }

    // 3) ONE big fp16 GEMM with fused fire2 scan -> writes sacc directly
    {
        dim3 grid(HH / 128, (TT * BB) / 128);
        gemm_big<<<grid, 256, SMBIG>>>(s1all, w2h, b2, sacc);
    }

    // 4) ONE small GEMM: v3 = sacc @ w3 + (255/256) b3
    {
        dim3 grid(1, BB / 128);
        gemm_g3<<<grid, 256, SMG3>>>(sacc, w3h, b3s, v3);
    }

    // 5) tanh-Gaussian head
    finalize_kernel<<<BB / 8, 256>>>(eps, out);
}

// round 11
// speedup vs baseline: 1.4628x; 1.1008x over previous
#include <cuda_runtime.h>
#include <cuda_fp16.h>
#include <cstdint>

// Problem constants
#define BB 8192
#define NN 128
#define HH 1024
#define OO 64      // 2*A
#define AA 32
#define TT 8

#define BH ((size_t)BB * HH)
#define BO ((size_t)BB * OO)

// ---------------------------------------------------------------------------
// Scratch (device globals — allocation-free per harness rules)
// ---------------------------------------------------------------------------
__device__ unsigned short g_s1all[TT * BH];      // s1 spikes, row m = b*8 + t, fp16 bits
__device__ unsigned short g_sacc [BH];           // sum_t 2^(t-8) s2(t), fp16 (exact)
__device__ float          g_v3   [BO];
__device__ unsigned short g_w2h[1024 * 2048];    // [N=1024][K=2048] fp16 hi|lo
__device__ unsigned short g_w3h[64 * 2048];      // [N=64]  [K=2048] fp16 hi|lo
__device__ float          g_b3s[OO];             // b3 * 255/256

// ---------------------------------------------------------------------------
// PTX helpers (baseline sm_103 ISA: cp.async, ldmatrix, mma.sync fp16)
// ---------------------------------------------------------------------------
__device__ __forceinline__ uint32_t smem_u32(const void* p) {
    uint32_t a;
    asm("{ .reg .u64 t; cvta.to.shared.u64 t, %1; cvt.u32.u64 %0, t; }" : "=r"(a) : "l"(p));
    return a;
}
__device__ __forceinline__ void cp16(uint32_t dst, const void* src) {
    asm volatile("cp.async.cg.shared.global [%0], [%1], 16;" :: "r"(dst), "l"(src));
}
#define CP_COMMIT() asm volatile("cp.async.commit_group;" ::: "memory")
#define CP_WAIT(n)  asm volatile("cp.async.wait_group %0;" :: "n"(n) : "memory")

__device__ __forceinline__ void ldsm4(uint32_t* r, uint32_t a) {
    asm volatile("ldmatrix.sync.aligned.m8n8.x4.shared.b16 {%0,%1,%2,%3}, [%4];"
                 : "=r"(r[0]), "=r"(r[1]), "=r"(r[2]), "=r"(r[3]) : "r"(a));
}
// fp16 HMMA with fp32 accumulation
__device__ __forceinline__ void mma16816(float* c, const uint32_t* a, const uint32_t* b) {
    asm volatile("mma.sync.aligned.m16n8k16.row.col.f32.f16.f16.f32 "
                 "{%0,%1,%2,%3}, {%4,%5,%6,%7}, {%8,%9}, {%0,%1,%2,%3};"
                 : "+f"(c[0]), "+f"(c[1]), "+f"(c[2]), "+f"(c[3])
                 : "r"(a[0]), "r"(a[1]), "r"(a[2]), "r"(a[3]), "r"(b[0]), "r"(b[1]));
}

// ---------------------------------------------------------------------------
// Weight prep via smem tile transpose (coalesced both sides).
// w2: [k=1024][n=1024] fp32 -> g_w2h [n][2048] fp16 hi|lo
// ---------------------------------------------------------------------------
__global__ void prep_w2h(const float* __restrict__ w2) {
    __shared__ float tile[32][33];
    const int bx = blockIdx.x, by = blockIdx.y;
    const int tx = threadIdx.x, ty = threadIdx.y;
#pragma unroll
    for (int i = ty; i < 32; i += 8)
        tile[i][tx] = w2[(size_t)(by * 32 + i) * 1024 + bx * 32 + tx];
    __syncthreads();
#pragma unroll
    for (int i = ty; i < 32; i += 8) {
        int n = bx * 32 + i, k = by * 32 + tx;
        float w = tile[tx][i];
        __half hi = __float2half_rn(w);
        __half lo = __float2half_rn(w - __half2float(hi));
        g_w2h[(size_t)n * 2048 + k]        = __half_as_ushort(hi);
        g_w2h[(size_t)n * 2048 + 1024 + k] = __half_as_ushort(lo);
    }
}
__global__ void prep_w3h(const float* __restrict__ w3, const float* __restrict__ b3) {
    int t = blockIdx.x * blockDim.x + threadIdx.x;            // 64K threads
    if (t >= 64 * 1024) return;
    int n = t & 63, k = t >> 6;
    float w = w3[(size_t)k * 64 + n];
    __half hi = __float2half_rn(w);
    __half lo = __float2half_rn(w - __half2float(hi));
    size_t base = (size_t)n * 2048;
    g_w3h[base + k]        = __half_as_ushort(hi);
    g_w3h[base + 1024 + k] = __half_as_ushort(lo);
    if (t < OO) g_b3s[t] = b3[t] * (255.0f / 256.0f);
}

#define EPAD 132   // padded row length (floats) for the fire2 epilogue tile

// ---------------------------------------------------------------------------
// g1 + fire1 fused (EXACT fp32; single accumulator, ascending k 0..127 —
// bit-identical to the round-9 passing kernel). Retiled for issue efficiency:
// BM=128, BN=128, BK=16, TM=8, TN=8 (two 4-col groups), 256 threads.
// Epilogue: all 8 IF-node-1 steps; spikes stored as ushort4 quads into
// g_s1all rows m = r*8 + t (fp16 0/1).
// ---------------------------------------------------------------------------
__global__ __launch_bounds__(256)
void g1_fire1(const float* __restrict__ A, const float* __restrict__ Bm,
              const float* __restrict__ bias)
{
    constexpr int BK = 16;
    __shared__ float As[BK][128 + 4];   // k-major: As[k][row]
    __shared__ float Bs[BK][128 + 4];   // Bs[k][col]
    const int tid = threadIdx.x;
    const int tx = tid & 15;            // 0..15 (col groups)
    const int ty = tid >> 4;            // 0..15 (row groups of 8)
    const int rowBase = blockIdx.y * 128;
    const int colBase = blockIdx.x * 128;

    float acc[8][8];
#pragma unroll
    for (int i = 0; i < 8; i++)
#pragma unroll
        for (int j = 0; j < 8; j++) acc[i][j] = 0.0f;

    for (int k0 = 0; k0 < NN; k0 += BK) {
        // A: 128 rows x 16 k = 512 float4 (along k), 2 per thread
#pragma unroll
        for (int i = tid; i < 512; i += 256) {
            int r = i >> 2, k4 = (i & 3) * 4;
            float4 v = *reinterpret_cast<const float4*>(
                A + (size_t)(rowBase + r) * NN + k0 + k4);
            As[k4 + 0][r] = v.x;
            As[k4 + 1][r] = v.y;
            As[k4 + 2][r] = v.z;
            As[k4 + 3][r] = v.w;
        }
        // B: 16 k-rows x 128 cols = 512 float4 (along cols), 2 per thread
#pragma unroll
        for (int i = tid; i < 512; i += 256) {
            int rr = i >> 5, c4 = (i & 31) * 4;
            float4 v = *reinterpret_cast<const float4*>(
                Bm + (size_t)(k0 + rr) * HH + colBase + c4);
            *reinterpret_cast<float4*>(&Bs[rr][c4]) = v;
        }
        __syncthreads();
#pragma unroll
        for (int kk = 0; kk < BK; kk++) {
            float4 ra0 = *reinterpret_cast<const float4*>(&As[kk][ty * 8]);
            float4 ra1 = *reinterpret_cast<const float4*>(&As[kk][ty * 8 + 4]);
            float4 rb0 = *reinterpret_cast<const float4*>(&Bs[kk][tx * 4]);
            float4 rb1 = *reinterpret_cast<const float4*>(&Bs[kk][64 + tx * 4]);
            float ra[8] = { ra0.x, ra0.y, ra0.z, ra0.w, ra1.x, ra1.y, ra1.z, ra1.w };
            float rb[8] = { rb0.x, rb0.y, rb0.z, rb0.w, rb1.x, rb1.y, rb1.z, rb1.w };
#pragma unroll
            for (int i = 0; i < 8; i++)
#pragma unroll
                for (int j = 0; j < 8; j++)
                    acc[i][j] += ra[i] * rb[j];
        }
        __syncthreads();
    }

    // fused fire1: per row, two 4-col groups; ushort4 spike stores.
    const int cg0 = colBase + tx * 4;
    const int cg1 = colBase + 64 + tx * 4;
    const float4 bv0 = *reinterpret_cast<const float4*>(bias + cg0);
    const float4 bv1 = *reinterpret_cast<const float4*>(bias + cg1);
#pragma unroll
    for (int i = 0; i < 8; i++) {
        int r = rowBase + ty * 8 + i;
        size_t rowb = (size_t)r * (TT * HH);
#pragma unroll
        for (int g = 0; g < 2; g++) {
            float u[4];
            if (g == 0) {
                u[0] = acc[i][0] + bv0.x; u[1] = acc[i][1] + bv0.y;
                u[2] = acc[i][2] + bv0.z; u[3] = acc[i][3] + bv0.w;
            } else {
                u[0] = acc[i][4] + bv1.x; u[1] = acc[i][5] + bv1.y;
                u[2] = acc[i][6] + bv1.z; u[3] = acc[i][7] + bv1.w;
            }
            int cg = (g == 0) ? cg0 : cg1;
            float v1[4] = { 0.0f, 0.0f, 0.0f, 0.0f };
#pragma unroll
            for (int t = 0; t < TT; ++t) {
                ushort4 sv;
                float h;
                h = v1[0] + u[0]; sv.x = (h >= 1.0f) ? 0x3C00 : 0; v1[0] = (h >= 1.0f) ? 0.0f : h;
                h = v1[1] + u[1]; sv.y = (h >= 1.0f) ? 0x3C00 : 0; v1[1] = (h >= 1.0f) ? 0.0f : h;
                h = v1[2] + u[2]; sv.z = (h >= 1.0f) ? 0x3C00 : 0; v1[2] = (h >= 1.0f) ? 0.0f : h;
                h = v1[3] + u[3]; sv.w = (h >= 1.0f) ? 0x3C00 : 0; v1[3] = (h >= 1.0f) ? 0.0f : h;
                *reinterpret_cast<ushort4*>(g_s1all + rowb + (size_t)t * HH + cg) = sv;
            }
        }
    }
}

// ---------------------------------------------------------------------------
// Big fp16 HMMA GEMM with FUSED fire2 scan via SMEM round-trip (round-9 verbatim).
// ---------------------------------------------------------------------------
__global__ __launch_bounds__(256, 2)
void gemm_big(const unsigned short* __restrict__ A,
              const unsigned short* __restrict__ Bt,
              const float* __restrict__ b2,
              unsigned short* __restrict__ saccp)
{
    constexpr int BK = 64;
    constexpr int KTOT = 2048, AK = 1024;
    constexpr int NIT = KTOT / BK;        // 32
    constexpr int STAGES = 3;
    constexpr int ATB = 128 * 128;
    constexpr int BTB = 128 * 128;
    constexpr int STAGE = ATB + BTB;

    extern __shared__ char dsm[];
    const uint32_t sbase = smem_u32(dsm);

    const int tid = threadIdx.x;
    const int wid = tid >> 5;
    const int lane = tid & 31;
    const int wm = wid & 3;
    const int wn = wid >> 2;
    const int rowBase = blockIdx.y * 128;
    const int colBase = blockIdx.x * 128;

    auto load_tile = [&](int buf, int it) {
        const uint32_t sA = sbase + buf * STAGE;
        const uint32_t sB = sA + ATB;
        const int kb = it * BK;
        const int kA = kb & (AK - 1);
#pragma unroll
        for (int i = 0; i < 4; ++i) {
            int idx = i * 256 + tid;
            int r = idx >> 3, q = idx & 7;
            const void* src = A + (size_t)(rowBase + r) * AK + kA + q * 8;
            cp16(sA + r * 128 + ((q ^ (r & 7)) << 4), src);
        }
#pragma unroll
        for (int i = 0; i < 4; ++i) {
            int idx = i * 256 + tid;
            int r = idx >> 3, q = idx & 7;
            const void* src = Bt + (size_t)(colBase + r) * KTOT + kb + q * 8;
            cp16(sB + r * 128 + ((q ^ (r & 7)) << 4), src);
        }
    };

    float acc[2][8][4];
#pragma unroll
    for (int mt = 0; mt < 2; ++mt)
#pragma unroll
        for (int nt = 0; nt < 8; ++nt)
#pragma unroll
            for (int x = 0; x < 4; ++x) acc[mt][nt][x] = 0.0f;

#pragma unroll
    for (int p = 0; p < STAGES - 1; ++p) { load_tile(p, p); CP_COMMIT(); }

    const int rA0 = wm * 32 + (lane & 15);
    const int qAsel = lane >> 4;
    const int nB0 = wn * 64 + ((lane >> 4) << 3) + (lane & 7);
    const int qBsel = (lane >> 3) & 1;

    for (int it = 0; it < NIT; ++it) {
        CP_WAIT(1);
        __syncthreads();
        if (it + STAGES - 1 < NIT) load_tile((it + STAGES - 1) % STAGES, it + STAGES - 1);
        CP_COMMIT();

        const uint32_t sA = sbase + (it % STAGES) * STAGE;
        const uint32_t sB = sA + ATB;

#pragma unroll
        for (int s = 0; s < 4; ++s) {
            uint32_t a[2][4];
#pragma unroll
            for (int mt = 0; mt < 2; ++mt) {
                int r = rA0 + mt * 16;
                int q = 2 * s + qAsel;
                ldsm4(a[mt], sA + r * 128 + ((q ^ (r & 7)) << 4));
            }
            uint32_t b[8][2];
#pragma unroll
            for (int j = 0; j < 8; j += 2) {
                int n = nB0 + j * 8;
                int q = 2 * s + qBsel;
                uint32_t t4[4];
                ldsm4(t4, sB + n * 128 + ((q ^ (n & 7)) << 4));
                b[j][0] = t4[0]; b[j][1] = t4[1];
                b[j + 1][0] = t4[2]; b[j + 1][1] = t4[3];
            }
#pragma unroll
            for (int mt = 0; mt < 2; ++mt)
#pragma unroll
                for (int nt = 0; nt < 8; ++nt)
                    mma16816(acc[mt][nt], a[mt], b[nt]);
        }
    }

    // ---- fused fire2 epilogue via smem ----
    CP_WAIT(0);
    __syncthreads();
    float* sx = reinterpret_cast<float*>(dsm);

#pragma unroll
    for (int mt = 0; mt < 2; ++mt) {
#pragma unroll
        for (int nt = 0; nt < 8; ++nt) {
            int c = wn * 64 + nt * 8 + (lane & 3) * 2;
#pragma unroll
            for (int hrow = 0; hrow < 2; ++hrow) {
                int m = wm * 32 + mt * 16 + (lane >> 2) + hrow * 8;
                float2 v;
                v.x = acc[mt][nt][hrow * 2 + 0];
                v.y = acc[mt][nt][hrow * 2 + 1];
                *reinterpret_cast<float2*>(&sx[m * EPAD + c]) = v;
            }
        }
    }
    __syncthreads();

    const int bBase = rowBase >> 3;
#pragma unroll
    for (int idx = 0; idx < 8; ++idx) {
        int flat = idx * 256 + tid;
        int bl = flat >> 7;
        int cl = flat & 127;
        float bi = b2[colBase + cl];
        float v2 = 0.0f, sc = 0.0f;
#pragma unroll
        for (int t = 0; t < TT; ++t) {
            float x = sx[(bl * 8 + t) * EPAD + cl];
            float h = v2 + x;          // (v2 + M)
            h = h + bi;                // ... + b2   (matches reference order)
            bool s = (h >= 1.0f);
            v2 = s ? 0.0f : h;
            if (s) sc += (float)(1 << t) * (1.0f / 256.0f);
        }
        saccp[(size_t)(bBase + bl) * HH + colBase + cl] =
            __half_as_ushort(__float2half_rn(sc));
    }
}

// ---------------------------------------------------------------------------
// Small fp16 GEMM for g3: v3 = sacc @ w3h^T + b3s.  K=2048 (hi|lo). Unchanged.
// ---------------------------------------------------------------------------
__global__ __launch_bounds__(256)
void gemm_g3(const unsigned short* __restrict__ A,
             const unsigned short* __restrict__ Bt,
             const float* __restrict__ bias,
             float* __restrict__ outp)
{
    constexpr int BM = 128, BN = 64, BK = 64;
    constexpr int KTOT = 2048, AK = 1024;
    constexpr int NIT = KTOT / BK;
    constexpr int STAGES = 3;
    constexpr int ATB = BM * 128;
    constexpr int BTB = BN * 128;
    constexpr int STAGE = ATB + BTB;
    constexpr int WTM = 16;

    extern __shared__ char dsm[];
    const uint32_t sbase = smem_u32(dsm);

    const int tid = threadIdx.x;
    const int wid = tid >> 5;
    const int lane = tid & 31;
    const int wm = wid;
    const int rowBase = blockIdx.y * BM;

    auto load_tile = [&](int buf, int it) {
        const uint32_t sA = sbase + buf * STAGE;
        const uint32_t sB = sA + ATB;
        const int kb = it * BK;
        const int kA = kb & (AK - 1);
#pragma unroll
        for (int i = 0; i < (BM * 8) / 256; ++i) {
            int idx = i * 256 + tid;
            int r = idx >> 3, q = idx & 7;
            const void* src = A + (size_t)(rowBase + r) * AK + kA + q * 8;
            cp16(sA + r * 128 + ((q ^ (r & 7)) << 4), src);
        }
#pragma unroll
        for (int i = 0; i < (BN * 8) / 256; ++i) {
            int idx = i * 256 + tid;
            int r = idx >> 3, q = idx & 7;
            const void* src = Bt + (size_t)r * KTOT + kb + q * 8;
            cp16(sB + r * 128 + ((q ^ (r & 7)) << 4), src);
        }
    };

    float acc[8][4];
#pragma unroll
    for (int nt = 0; nt < 8; ++nt)
#pragma unroll
        for (int x = 0; x < 4; ++x) acc[nt][x] = 0.0f;

#pragma unroll
    for (int p = 0; p < STAGES - 1; ++p) { load_tile(p, p); CP_COMMIT(); }

    const int rA0 = wm * WTM + (lane & 15);
    const int qAsel = lane >> 4;
    const int nB0 = (lane >> 4) * 8 + (lane & 7);
    const int qBsel = (lane >> 3) & 1;

    for (int it = 0; it < NIT; ++it) {
        CP_WAIT(1);
        __syncthreads();
        if (it + STAGES - 1 < NIT) load_tile((it + STAGES - 1) % STAGES, it + STAGES - 1);
        CP_COMMIT();

        const uint32_t sA = sbase + (it % STAGES) * STAGE;
        const uint32_t sB = sA + ATB;

#pragma unroll
        for (int s = 0; s < 4; ++s) {
            uint32_t a[4];
            {
                int r = rA0;
                int q = 2 * s + qAsel;
                ldsm4(a, sA + r * 128 + ((q ^ (r & 7)) << 4));
            }
            uint32_t b[8][2];
#pragma unroll
            for (int j = 0; j < 8; j += 2) {
                int n = nB0 + j * 8;
                int q = 2 * s + qBsel;
                uint32_t t4[4];
                ldsm4(t4, sB + n * 128 + ((q ^ (n & 7)) << 4));
                b[j][0] = t4[0]; b[j][1] = t4[1];
                b[j + 1][0] = t4[2]; b[j + 1][1] = t4[3];
            }
#pragma unroll
            for (int nt = 0; nt < 8; ++nt)
                mma16816(acc[nt], a, b[nt]);
        }
    }

    int r0 = rowBase + wm * WTM + (lane >> 2);
#pragma unroll
    for (int nt = 0; nt < 8; ++nt) {
        int c = nt * 8 + (lane & 3) * 2;
        float bi0 = bias[c], bi1 = bias[c + 1];
#pragma unroll
        for (int hrow = 0; hrow < 2; ++hrow) {
            int r = r0 + hrow * 8;
            size_t idx = (size_t)r * OO + c;
            float2 o;
            o.x = acc[nt][hrow * 2 + 0] + bi0;
            o.y = acc[nt][hrow * 2 + 1] + bi1;
            *reinterpret_cast<float2*>(outp + idx) = o;
        }
    }
}

// ---------------------------------------------------------------------------
// Final tanh-Gaussian epilogue. One warp per batch row. Unchanged.
// ---------------------------------------------------------------------------
__global__ void finalize_kernel(const float* __restrict__ eps, float* __restrict__ out) {
    int warp = (blockIdx.x * blockDim.x + threadIdx.x) >> 5;
    int lane = threadIdx.x & 31;
    if (warp >= BB) return;
    const float* v3r = g_v3 + (size_t)warp * OO;
    float mu = v3r[lane];
    float ls = v3r[AA + lane];
    ls = fminf(fmaxf(ls, -20.0f), 2.0f);
    float sd = expf(ls);
    float e  = eps[(size_t)warp * AA + lane];
    float z  = mu + sd * e;
    float a  = tanhf(z);
    out[(size_t)warp * AA + lane] = a;
    float lp = -0.5f * e * e - ls - 0.91893853320467274f
               - logf(1.0f - a * a + 1e-7f);
#pragma unroll
    for (int o = 16; o > 0; o >>= 1) lp += __shfl_down_sync(0xffffffffu, lp, o);
    if (lane == 0) out[(size_t)BB * AA + warp] = lp;
}

// ---------------------------------------------------------------------------
extern "C" void kernel_launch(void* const* d_in, const int* in_sizes, int n_in,
                              void* d_out, int out_size)
{
    const float* state = (const float*)d_in[0];
    const float* w1    = (const float*)d_in[1];
    const float* b1    = (const float*)d_in[2];
    const float* w2    = (const float*)d_in[3];
    const float* b2    = (const float*)d_in[4];
    const float* w3    = (const float*)d_in[5];
    const float* b3    = (const float*)d_in[6];
    const float* eps   = (const float*)d_in[7];
    float* out = (float*)d_out;

    float* v3 = nullptr;
    unsigned short* s1all = nullptr; unsigned short* sacc = nullptr;
    unsigned short* w2h = nullptr; unsigned short* w3h = nullptr;
    float* b3s = nullptr;
    cudaGetSymbolAddress((void**)&v3,    g_v3);
    cudaGetSymbolAddress((void**)&s1all, g_s1all);
    cudaGetSymbolAddress((void**)&sacc,  g_sacc);
    cudaGetSymbolAddress((void**)&w2h,   g_w2h);
    cudaGetSymbolAddress((void**)&w3h,   g_w3h);
    cudaGetSymbolAddress((void**)&b3s,   g_b3s);

    const int SMBIG = 3 * (128 * 128 + 128 * 128); // 98304 (>= 128*EPAD*4)
    const int SMG3  = 3 * (128 * 128 + 64 * 128);  // 73728
    cudaFuncSetAttribute(gemm_big, cudaFuncAttributeMaxDynamicSharedMemorySize, SMBIG);
    cudaFuncSetAttribute(gemm_g3,  cudaFuncAttributeMaxDynamicSharedMemorySize, SMG3);

    // 1) weight prep (2-term fp16 split; w2 via coalesced tile transpose)
    {
        dim3 blk(32, 8);
        prep_w2h<<<dim3(32, 32), blk>>>(w2);
    }
    prep_w3h<<<(64 * 1024) / 256, 256>>>(w3, b3);

    // 2) g1 (exact fp32, ascending-k — bit-identical to round 9) + fused fire1
    {
        dim3 grid(HH / 128, BB / 128);
        g1_fire1<<<grid, 256>>>(state, w1, b1);
    }

    // 3) big fp16 GEMM with fused fire2 scan -> writes sacc directly
    {
        dim3 grid(HH / 128, (TT * BB) / 128);
        gemm_big<<<grid, 256, SMBIG>>>(s1all, w2h, b2, sacc);
    }

    // 4) small GEMM: v3 = sacc @ w3 + (255/256) b3
    {
        dim3 grid(1, BB / 128);
        gemm_g3<<<grid, 256, SMG3>>>(sacc, w3h, b3s, v3);
    }

    // 5) tanh-Gaussian head
    finalize_kernel<<<BB / 8, 256>>>(eps, out);
}

// round 12
// speedup vs baseline: 1.4879x; 1.0172x over previous
#include <cuda_runtime.h>
#include <cuda_fp16.h>
#include <cstdint>

// Problem constants
#define BB 8192
#define NN 128
#define HH 1024
#define OO 64      // 2*A
#define AA 32
#define TT 8

#define BH ((size_t)BB * HH)
#define BO ((size_t)BB * OO)

// ---------------------------------------------------------------------------
// Scratch (device globals — allocation-free per harness rules)
// ---------------------------------------------------------------------------
__device__ unsigned short g_s1all[TT * BH];      // s1 spikes, row m = b*8 + t, fp16 bits
__device__ unsigned short g_sacc [BH];           // sum_t 2^(t-8) s2(t), fp16 (exact)
__device__ float          g_v3   [BO];
__device__ unsigned short g_w2h[1024 * 2048];    // [N=1024][K=2048] fp16 hi|lo
__device__ unsigned short g_w3h[64 * 2048];      // [N=64]  [K=2048] fp16 hi|lo
__device__ float          g_b3s[OO];             // b3 * 255/256

// ---------------------------------------------------------------------------
// PTX helpers (baseline sm_103 ISA: cp.async, ldmatrix, mma.sync fp16)
// ---------------------------------------------------------------------------
__device__ __forceinline__ uint32_t smem_u32(const void* p) {
    uint32_t a;
    asm("{ .reg .u64 t; cvta.to.shared.u64 t, %1; cvt.u32.u64 %0, t; }" : "=r"(a) : "l"(p));
    return a;
}
__device__ __forceinline__ void cp16(uint32_t dst, const void* src) {
    asm volatile("cp.async.cg.shared.global [%0], [%1], 16;" :: "r"(dst), "l"(src));
}
#define CP_COMMIT() asm volatile("cp.async.commit_group;" ::: "memory")
#define CP_WAIT(n)  asm volatile("cp.async.wait_group %0;" :: "n"(n) : "memory")

__device__ __forceinline__ void ldsm4(uint32_t* r, uint32_t a) {
    asm volatile("ldmatrix.sync.aligned.m8n8.x4.shared.b16 {%0,%1,%2,%3}, [%4];"
                 : "=r"(r[0]), "=r"(r[1]), "=r"(r[2]), "=r"(r[3]) : "r"(a));
}
// fp16 HMMA with fp32 accumulation
__device__ __forceinline__ void mma16816(float* c, const uint32_t* a, const uint32_t* b) {
    asm volatile("mma.sync.aligned.m16n8k16.row.col.f32.f16.f16.f32 "
                 "{%0,%1,%2,%3}, {%4,%5,%6,%7}, {%8,%9}, {%0,%1,%2,%3};"
                 : "+f"(c[0]), "+f"(c[1]), "+f"(c[2]), "+f"(c[3])
                 : "r"(a[0]), "r"(a[1]), "r"(a[2]), "r"(a[3]), "r"(b[0]), "r"(b[1]));
}

// ---------------------------------------------------------------------------
// Weight prep via smem tile transpose (coalesced both sides).
// w2: [k=1024][n=1024] fp32 -> g_w2h [n][2048] fp16 hi|lo
// ---------------------------------------------------------------------------
__global__ void prep_w2h(const float* __restrict__ w2) {
    __shared__ float tile[32][33];
    const int bx = blockIdx.x, by = blockIdx.y;
    const int tx = threadIdx.x, ty = threadIdx.y;
#pragma unroll
    for (int i = ty; i < 32; i += 8)
        tile[i][tx] = w2[(size_t)(by * 32 + i) * 1024 + bx * 32 + tx];
    __syncthreads();
#pragma unroll
    for (int i = ty; i < 32; i += 8) {
        int n = bx * 32 + i, k = by * 32 + tx;
        float w = tile[tx][i];
        __half hi = __float2half_rn(w);
        __half lo = __float2half_rn(w - __half2float(hi));
        g_w2h[(size_t)n * 2048 + k]        = __half_as_ushort(hi);
        g_w2h[(size_t)n * 2048 + 1024 + k] = __half_as_ushort(lo);
    }
}
__global__ void prep_w3h(const float* __restrict__ w3, const float* __restrict__ b3) {
    int t = blockIdx.x * blockDim.x + threadIdx.x;            // 64K threads
    if (t >= 64 * 1024) return;
    int n = t & 63, k = t >> 6;
    float w = w3[(size_t)k * 64 + n];
    __half hi = __float2half_rn(w);
    __half lo = __float2half_rn(w - __half2float(hi));
    size_t base = (size_t)n * 2048;
    g_w3h[base + k]        = __half_as_ushort(hi);
    g_w3h[base + 1024 + k] = __half_as_ushort(lo);
    if (t < OO) g_b3s[t] = b3[t] * (255.0f / 256.0f);
}

#define EPAD 132   // padded row length (floats) for the fire2 epilogue tile; 132*4B = 16B-aligned rows

// ---------------------------------------------------------------------------
// g1 + fire1 fused (EXACT fp32; single accumulator, ascending k 0..127 —
// bit-identical u). BM=128, BN=128, BK=16, TM=8, TN=8, 256 threads.
// Epilogue: all 8 IF-node-1 steps; ushort4 spike stores, rows m = r*8 + t.
// ---------------------------------------------------------------------------
__global__ __launch_bounds__(256)
void g1_fire1(const float* __restrict__ A, const float* __restrict__ Bm,
              const float* __restrict__ bias)
{
    constexpr int BK = 16;
    __shared__ float As[BK][128 + 4];   // k-major: As[k][row]
    __shared__ float Bs[BK][128 + 4];   // Bs[k][col]
    const int tid = threadIdx.x;
    const int tx = tid & 15;            // 0..15 (col groups)
    const int ty = tid >> 4;            // 0..15 (row groups of 8)
    const int rowBase = blockIdx.y * 128;
    const int colBase = blockIdx.x * 128;

    float acc[8][8];
#pragma unroll
    for (int i = 0; i < 8; i++)
#pragma unroll
        for (int j = 0; j < 8; j++) acc[i][j] = 0.0f;

    for (int k0 = 0; k0 < NN; k0 += BK) {
#pragma unroll
        for (int i = tid; i < 512; i += 256) {
            int r = i >> 2, k4 = (i & 3) * 4;
            float4 v = *reinterpret_cast<const float4*>(
                A + (size_t)(rowBase + r) * NN + k0 + k4);
            As[k4 + 0][r] = v.x;
            As[k4 + 1][r] = v.y;
            As[k4 + 2][r] = v.z;
            As[k4 + 3][r] = v.w;
        }
#pragma unroll
        for (int i = tid; i < 512; i += 256) {
            int rr = i >> 5, c4 = (i & 31) * 4;
            float4 v = *reinterpret_cast<const float4*>(
                Bm + (size_t)(k0 + rr) * HH + colBase + c4);
            *reinterpret_cast<float4*>(&Bs[rr][c4]) = v;
        }
        __syncthreads();
#pragma unroll
        for (int kk = 0; kk < BK; kk++) {
            float4 ra0 = *reinterpret_cast<const float4*>(&As[kk][ty * 8]);
            float4 ra1 = *reinterpret_cast<const float4*>(&As[kk][ty * 8 + 4]);
            float4 rb0 = *reinterpret_cast<const float4*>(&Bs[kk][tx * 4]);
            float4 rb1 = *reinterpret_cast<const float4*>(&Bs[kk][64 + tx * 4]);
            float ra[8] = { ra0.x, ra0.y, ra0.z, ra0.w, ra1.x, ra1.y, ra1.z, ra1.w };
            float rb[8] = { rb0.x, rb0.y, rb0.z, rb0.w, rb1.x, rb1.y, rb1.z, rb1.w };
#pragma unroll
            for (int i = 0; i < 8; i++)
#pragma unroll
                for (int j = 0; j < 8; j++)
                    acc[i][j] += ra[i] * rb[j];
        }
        __syncthreads();
    }

    const int cg0 = colBase + tx * 4;
    const int cg1 = colBase + 64 + tx * 4;
    const float4 bv0 = *reinterpret_cast<const float4*>(bias + cg0);
    const float4 bv1 = *reinterpret_cast<const float4*>(bias + cg1);
#pragma unroll
    for (int i = 0; i < 8; i++) {
        int r = rowBase + ty * 8 + i;
        size_t rowb = (size_t)r * (TT * HH);
#pragma unroll
        for (int g = 0; g < 2; g++) {
            float u[4];
            if (g == 0) {
                u[0] = acc[i][0] + bv0.x; u[1] = acc[i][1] + bv0.y;
                u[2] = acc[i][2] + bv0.z; u[3] = acc[i][3] + bv0.w;
            } else {
                u[0] = acc[i][4] + bv1.x; u[1] = acc[i][5] + bv1.y;
                u[2] = acc[i][6] + bv1.z; u[3] = acc[i][7] + bv1.w;
            }
            int cg = (g == 0) ? cg0 : cg1;
            float v1[4] = { 0.0f, 0.0f, 0.0f, 0.0f };
#pragma unroll
            for (int t = 0; t < TT; ++t) {
                ushort4 sv;
                float h;
                h = v1[0] + u[0]; sv.x = (h >= 1.0f) ? 0x3C00 : 0; v1[0] = (h >= 1.0f) ? 0.0f : h;
                h = v1[1] + u[1]; sv.y = (h >= 1.0f) ? 0x3C00 : 0; v1[1] = (h >= 1.0f) ? 0.0f : h;
                h = v1[2] + u[2]; sv.z = (h >= 1.0f) ? 0x3C00 : 0; v1[2] = (h >= 1.0f) ? 0.0f : h;
                h = v1[3] + u[3]; sv.w = (h >= 1.0f) ? 0x3C00 : 0; v1[3] = (h >= 1.0f) ? 0.0f : h;
                *reinterpret_cast<ushort4*>(g_s1all + rowb + (size_t)t * HH + cg) = sv;
            }
        }
    }
}

// ---------------------------------------------------------------------------
// Big fp16 HMMA GEMM with FUSED fire2 scan via SMEM round-trip.
// Epilogue scan re-tasked: 2 tasks/thread of (row, 4-col group) using LDS.128
// and ushort4 sacc stores (same per-element fp32 scan sequence — bit-identical).
// ---------------------------------------------------------------------------
__global__ __launch_bounds__(256, 2)
void gemm_big(const unsigned short* __restrict__ A,
              const unsigned short* __restrict__ Bt,
              const float* __restrict__ b2,
              unsigned short* __restrict__ saccp)
{
    constexpr int BK = 64;
    constexpr int KTOT = 2048, AK = 1024;
    constexpr int NIT = KTOT / BK;        // 32
    constexpr int STAGES = 3;
    constexpr int ATB = 128 * 128;
    constexpr int BTB = 128 * 128;
    constexpr int STAGE = ATB + BTB;

    extern __shared__ char dsm[];
    const uint32_t sbase = smem_u32(dsm);

    const int tid = threadIdx.x;
    const int wid = tid >> 5;
    const int lane = tid & 31;
    const int wm = wid & 3;
    const int wn = wid >> 2;
    const int rowBase = blockIdx.y * 128;
    const int colBase = blockIdx.x * 128;

    auto load_tile = [&](int buf, int it) {
        const uint32_t sA = sbase + buf * STAGE;
        const uint32_t sB = sA + ATB;
        const int kb = it * BK;
        const int kA = kb & (AK - 1);
#pragma unroll
        for (int i = 0; i < 4; ++i) {
            int idx = i * 256 + tid;
            int r = idx >> 3, q = idx & 7;
            const void* src = A + (size_t)(rowBase + r) * AK + kA + q * 8;
            cp16(sA + r * 128 + ((q ^ (r & 7)) << 4), src);
        }
#pragma unroll
        for (int i = 0; i < 4; ++i) {
            int idx = i * 256 + tid;
            int r = idx >> 3, q = idx & 7;
            const void* src = Bt + (size_t)(colBase + r) * KTOT + kb + q * 8;
            cp16(sB + r * 128 + ((q ^ (r & 7)) << 4), src);
        }
    };

    float acc[2][8][4];
#pragma unroll
    for (int mt = 0; mt < 2; ++mt)
#pragma unroll
        for (int nt = 0; nt < 8; ++nt)
#pragma unroll
            for (int x = 0; x < 4; ++x) acc[mt][nt][x] = 0.0f;

#pragma unroll
    for (int p = 0; p < STAGES - 1; ++p) { load_tile(p, p); CP_COMMIT(); }

    const int rA0 = wm * 32 + (lane & 15);
    const int qAsel = lane >> 4;
    const int nB0 = wn * 64 + ((lane >> 4) << 3) + (lane & 7);
    const int qBsel = (lane >> 3) & 1;

    for (int it = 0; it < NIT; ++it) {
        CP_WAIT(1);
        __syncthreads();
        if (it + STAGES - 1 < NIT) load_tile((it + STAGES - 1) % STAGES, it + STAGES - 1);
        CP_COMMIT();

        const uint32_t sA = sbase + (it % STAGES) * STAGE;
        const uint32_t sB = sA + ATB;

#pragma unroll
        for (int s = 0; s < 4; ++s) {
            uint32_t a[2][4];
#pragma unroll
            for (int mt = 0; mt < 2; ++mt) {
                int r = rA0 + mt * 16;
                int q = 2 * s + qAsel;
                ldsm4(a[mt], sA + r * 128 + ((q ^ (r & 7)) << 4));
            }
            uint32_t b[8][2];
#pragma unroll
            for (int j = 0; j < 8; j += 2) {
                int n = nB0 + j * 8;
                int q = 2 * s + qBsel;
                uint32_t t4[4];
                ldsm4(t4, sB + n * 128 + ((q ^ (n & 7)) << 4));
                b[j][0] = t4[0]; b[j][1] = t4[1];
                b[j + 1][0] = t4[2]; b[j + 1][1] = t4[3];
            }
#pragma unroll
            for (int mt = 0; mt < 2; ++mt)
#pragma unroll
                for (int nt = 0; nt < 8; ++nt)
                    mma16816(acc[mt][nt], a[mt], b[nt]);
        }
    }

    // ---- fused fire2 epilogue via smem ----
    CP_WAIT(0);
    __syncthreads();
    float* sx = reinterpret_cast<float*>(dsm);

#pragma unroll
    for (int mt = 0; mt < 2; ++mt) {
#pragma unroll
        for (int nt = 0; nt < 8; ++nt) {
            int c = wn * 64 + nt * 8 + (lane & 3) * 2;
#pragma unroll
            for (int hrow = 0; hrow < 2; ++hrow) {
                int m = wm * 32 + mt * 16 + (lane >> 2) + hrow * 8;
                float2 v;
                v.x = acc[mt][nt][hrow * 2 + 0];
                v.y = acc[mt][nt][hrow * 2 + 1];
                *reinterpret_cast<float2*>(&sx[m * EPAD + c]) = v;
            }
        }
    }
    __syncthreads();

    // scan: 16 batch rows x 32 col-quads = 512 tasks, 2 per thread, LDS.128.
    const int bBase = rowBase >> 3;
#pragma unroll
    for (int idx = 0; idx < 2; ++idx) {
        int flat = idx * 256 + tid;
        int bl = flat >> 5;             // 0..15
        int c4 = (flat & 31) * 4;       // 0..124
        const float4 bv = *reinterpret_cast<const float4*>(&b2[colBase + c4]);
        float v2[4] = { 0.0f, 0.0f, 0.0f, 0.0f };
        float sc[4] = { 0.0f, 0.0f, 0.0f, 0.0f };
#pragma unroll
        for (int t = 0; t < TT; ++t) {
            float4 x = *reinterpret_cast<const float4*>(&sx[(bl * 8 + t) * EPAD + c4]);
            float w = (float)(1 << t) * (1.0f / 256.0f);
            float h;
            h = v2[0] + x.x; h = h + bv.x;
            if (h >= 1.0f) { v2[0] = 0.0f; sc[0] += w; } else v2[0] = h;
            h = v2[1] + x.y; h = h + bv.y;
            if (h >= 1.0f) { v2[1] = 0.0f; sc[1] += w; } else v2[1] = h;
            h = v2[2] + x.z; h = h + bv.z;
            if (h >= 1.0f) { v2[2] = 0.0f; sc[2] += w; } else v2[2] = h;
            h = v2[3] + x.w; h = h + bv.w;
            if (h >= 1.0f) { v2[3] = 0.0f; sc[3] += w; } else v2[3] = h;
        }
        ushort4 sv;
        sv.x = __half_as_ushort(__float2half_rn(sc[0]));
        sv.y = __half_as_ushort(__float2half_rn(sc[1]));
        sv.z = __half_as_ushort(__float2half_rn(sc[2]));
        sv.w = __half_as_ushort(__float2half_rn(sc[3]));
        *reinterpret_cast<ushort4*>(
            saccp + (size_t)(bBase + bl) * HH + colBase + c4) = sv;
    }
}

// ---------------------------------------------------------------------------
// Small fp16 GEMM for g3: v3 = sacc @ w3h^T + b3s.  K=2048 (hi|lo).
// BM=64, 4 warps / 128 threads -> grid 128 CTAs (was 64). k-order unchanged.
// ---------------------------------------------------------------------------
__global__ __launch_bounds__(128)
void gemm_g3(const unsigned short* __restrict__ A,
             const unsigned short* __restrict__ Bt,
             const float* __restrict__ bias,
             float* __restrict__ outp)
{
    constexpr int BM = 64, BN = 64, BK = 64;
    constexpr int KTOT = 2048, AK = 1024;
    constexpr int NIT = KTOT / BK;        // 32
    constexpr int STAGES = 3;
    constexpr int ATB = BM * 128;         // 8192
    constexpr int BTB = BN * 128;         // 8192
    constexpr int STAGE = ATB + BTB;      // 16384
    constexpr int WTM = 16;

    extern __shared__ char dsm[];
    const uint32_t sbase = smem_u32(dsm);

    const int tid = threadIdx.x;
    const int wid = tid >> 5;             // 0..3
    const int lane = tid & 31;
    const int wm = wid;
    const int rowBase = blockIdx.y * BM;

    auto load_tile = [&](int buf, int it) {
        const uint32_t sA = sbase + buf * STAGE;
        const uint32_t sB = sA + ATB;
        const int kb = it * BK;
        const int kA = kb & (AK - 1);
#pragma unroll
        for (int i = 0; i < (BM * 8) / 128; ++i) {    // 4
            int idx = i * 128 + tid;
            int r = idx >> 3, q = idx & 7;
            const void* src = A + (size_t)(rowBase + r) * AK + kA + q * 8;
            cp16(sA + r * 128 + ((q ^ (r & 7)) << 4), src);
        }
#pragma unroll
        for (int i = 0; i < (BN * 8) / 128; ++i) {    // 4
            int idx = i * 128 + tid;
            int r = idx >> 3, q = idx & 7;
            const void* src = Bt + (size_t)r * KTOT + kb + q * 8;
            cp16(sB + r * 128 + ((q ^ (r & 7)) << 4), src);
        }
    };

    float acc[8][4];
#pragma unroll
    for (int nt = 0; nt < 8; ++nt)
#pragma unroll
        for (int x = 0; x < 4; ++x) acc[nt][x] = 0.0f;

#pragma unroll
    for (int p = 0; p < STAGES - 1; ++p) { load_tile(p, p); CP_COMMIT(); }

    const int rA0 = wm * WTM + (lane & 15);
    const int qAsel = lane >> 4;
    const int nB0 = (lane >> 4) * 8 + (lane & 7);
    const int qBsel = (lane >> 3) & 1;

    for (int it = 0; it < NIT; ++it) {
        CP_WAIT(1);
        __syncthreads();
        if (it + STAGES - 1 < NIT) load_tile((it + STAGES - 1) % STAGES, it + STAGES - 1);
        CP_COMMIT();

        const uint32_t sA = sbase + (it % STAGES) * STAGE;
        const uint32_t sB = sA + ATB;

#pragma unroll
        for (int s = 0; s < 4; ++s) {
            uint32_t a[4];
            {
                int r = rA0;
                int q = 2 * s + qAsel;
                ldsm4(a, sA + r * 128 + ((q ^ (r & 7)) << 4));
            }
            uint32_t b[8][2];
#pragma unroll
            for (int j = 0; j < 8; j += 2) {
                int n = nB0 + j * 8;
                int q = 2 * s + qBsel;
                uint32_t t4[4];
                ldsm4(t4, sB + n * 128 + ((q ^ (n & 7)) << 4));
                b[j][0] = t4[0]; b[j][1] = t4[1];
                b[j + 1][0] = t4[2]; b[j + 1][1] = t4[3];
            }
#pragma unroll
            for (int nt = 0; nt < 8; ++nt)
                mma16816(acc[nt], a, b[nt]);
        }
    }

    int r0 = rowBase + wm * WTM + (lane >> 2);
#pragma unroll
    for (int nt = 0; nt < 8; ++nt) {
        int c = nt * 8 + (lane & 3) * 2;
        float bi0 = bias[c], bi1 = bias[c + 1];
#pragma unroll
        for (int hrow = 0; hrow < 2; ++hrow) {
            int r = r0 + hrow * 8;
            size_t idx = (size_t)r * OO + c;
            float2 o;
            o.x = acc[nt][hrow * 2 + 0] + bi0;
            o.y = acc[nt][hrow * 2 + 1] + bi1;
            *reinterpret_cast<float2*>(outp + idx) = o;
        }
    }
}

// ---------------------------------------------------------------------------
// Final tanh-Gaussian epilogue. One warp per batch row. Unchanged.
// ---------------------------------------------------------------------------
__global__ void finalize_kernel(const float* __restrict__ eps, float* __restrict__ out) {
    int warp = (blockIdx.x * blockDim.x + threadIdx.x) >> 5;
    int lane = threadIdx.x & 31;
    if (warp >= BB) return;
    const float* v3r = g_v3 + (size_t)warp * OO;
    float mu = v3r[lane];
    float ls = v3r[AA + lane];
    ls = fminf(fmaxf(ls, -20.0f), 2.0f);
    float sd = expf(ls);
    float e  = eps[(size_t)warp * AA + lane];
    float z  = mu + sd * e;
    float a  = tanhf(z);
    out[(size_t)warp * AA + lane] = a;
    float lp = -0.5f * e * e - ls - 0.91893853320467274f
               - logf(1.0f - a * a + 1e-7f);
#pragma unroll
    for (int o = 16; o > 0; o >>= 1) lp += __shfl_down_sync(0xffffffffu, lp, o);
    if (lane == 0) out[(size_t)BB * AA + warp] = lp;
}

// ---------------------------------------------------------------------------
extern "C" void kernel_launch(void* const* d_in, const int* in_sizes, int n_in,
                              void* d_out, int out_size)
{
    const float* state = (const float*)d_in[0];
    const float* w1    = (const float*)d_in[1];
    const float* b1    = (const float*)d_in[2];
    const float* w2    = (const float*)d_in[3];
    const float* b2    = (const float*)d_in[4];
    const float* w3    = (const float*)d_in[5];
    const float* b3    = (const float*)d_in[6];
    const float* eps   = (const float*)d_in[7];
    float* out = (float*)d_out;

    float* v3 = nullptr;
    unsigned short* s1all = nullptr; unsigned short* sacc = nullptr;
    unsigned short* w2h = nullptr; unsigned short* w3h = nullptr;
    float* b3s = nullptr;
    cudaGetSymbolAddress((void**)&v3,    g_v3);
    cudaGetSymbolAddress((void**)&s1all, g_s1all);
    cudaGetSymbolAddress((void**)&sacc,  g_sacc);
    cudaGetSymbolAddress((void**)&w2h,   g_w2h);
    cudaGetSymbolAddress((void**)&w3h,   g_w3h);
    cudaGetSymbolAddress((void**)&b3s,   g_b3s);

    const int SMBIG = 3 * (128 * 128 + 128 * 128); // 98304 (>= 128*EPAD*4)
    const int SMG3  = 3 * (64 * 128 + 64 * 128);   // 49152
    cudaFuncSetAttribute(gemm_big, cudaFuncAttributeMaxDynamicSharedMemorySize, SMBIG);
    cudaFuncSetAttribute(gemm_g3,  cudaFuncAttributeMaxDynamicSharedMemorySize, SMG3);

    // 1) weight prep (2-term fp16 split; w2 via coalesced tile transpose)
    {
        dim3 blk(32, 8);
        prep_w2h<<<dim3(32, 32), blk>>>(w2);
    }
    prep_w3h<<<(64 * 1024) / 256, 256>>>(w3, b3);

    // 2) g1 (exact fp32, ascending-k) + fused fire1
    {
        dim3 grid(HH / 128, BB / 128);
        g1_fire1<<<grid, 256>>>(state, w1, b1);
    }

    // 3) big fp16 GEMM with fused fire2 scan -> writes sacc directly
    {
        dim3 grid(HH / 128, (TT * BB) / 128);
        gemm_big<<<grid, 256, SMBIG>>>(s1all, w2h, b2, sacc);
    }

    // 4) small GEMM: v3 = sacc @ w3 + (255/256) b3   (now 128 CTAs)
    {
        dim3 grid(1, BB / 64);
        gemm_g3<<<grid, 128, SMG3>>>(sacc, w3h, b3s, v3);
    }

    // 5) tanh-Gaussian head
    finalize_kernel<<<BB / 8, 256>>>(eps, out);
}